// round 4
// baseline (speedup 1.0000x reference)
#include <cuda_runtime.h>
#include <math.h>
#include <float.h>

// ---------------- problem constants (fixed by setup_inputs) ----------------
static constexpr int NCAM = 6;
static constexpr int CCH  = 64;
static constexpr int HF   = 64;
static constexpr int WF   = 176;
static constexpr int SLICE = HF * WF;          // 11264
static constexpr int ZD   = 129;
static constexpr int XD   = 129;
static constexpr int NY   = 4;
static constexpr int NH   = 3;                 // NY-1
static constexpr int DD   = 128;               // ZD-1
static constexpr int WDIM = 128;               // XD-1
static constexpr int P    = DD * WDIM;         // 16384 = 2^14
static constexpr int NREC = NCAM * NH * P;     // 294912
static constexpr float EPS_F = 1e-6f;

// ---------------- device scratch (no dynamic allocation allowed) -----------
__device__ float  d_integ [NCAM * CCH * SLICE];      // integral, [cam][ch][pix]
__device__ float  d_integT[NCAM * SLICE * CCH];      // integral, [cam][pix][ch]
__device__ float2 d_proj[NCAM * NY * ZD * XD];       // projected grid
__device__ int4   g_xi[NREC];                        // 4 column indices
__device__ int4   g_yo[NREC];                        // 4 row offsets (y*WF)
__device__ float4 g_wa[NREC];                        // 4 signed column weights
__device__ float4 g_wb[NREC];                        // 4 signed row weights
__device__ float  g_sc[NREC];                        // 1/area (0 if degenerate)

// ---------------- kernel 1: per-(cam,channel) 2D integral image -------------
__global__ void oft_integral(const float* __restrict__ feat) {
    __shared__ float sh[HF][WF + 1];
    const int s = blockIdx.x;          // 0..NCAM*CCH-1
    const float* src = feat + (size_t)s * SLICE;
    float* dst = d_integ + (size_t)s * SLICE;

    for (int i = threadIdx.x; i < SLICE; i += blockDim.x)
        sh[i / WF][i % WF] = src[i];
    __syncthreads();

    if (threadIdx.x < HF) {            // row-wise prefix sum
        float acc = 0.f;
        #pragma unroll 4
        for (int w = 0; w < WF; ++w) { acc += sh[threadIdx.x][w]; sh[threadIdx.x][w] = acc; }
    }
    __syncthreads();

    if (threadIdx.x < WF) {            // column-wise prefix sum
        float acc = 0.f;
        #pragma unroll 4
        for (int h = 0; h < HF; ++h) { acc += sh[h][threadIdx.x]; sh[h][threadIdx.x] = acc; }
    }
    __syncthreads();

    for (int i = threadIdx.x; i < SLICE; i += blockDim.x)
        dst[i] = sh[i / WF][i % WF];
}

// ---------------- kernel 1b: transpose to channel-last [cam][pix][ch] -------
__global__ void oft_transpose() {
    __shared__ float tile[32][33];
    const int cam = blockIdx.z;
    const int pixBase = blockIdx.x * 32;
    const int chBase  = blockIdx.y * 32;
    const int tx = threadIdx.x, ty = threadIdx.y;   // 32 x 8

    #pragma unroll
    for (int k = 0; k < 4; ++k) {
        const int ch = chBase + ty + 8 * k;
        tile[ty + 8 * k][tx] = d_integ[((size_t)(cam * CCH + ch)) * SLICE + pixBase + tx];
    }
    __syncthreads();
    #pragma unroll
    for (int k = 0; k < 4; ++k) {
        const int pix = pixBase + ty + 8 * k;
        d_integT[((size_t)cam * SLICE + pix) * CCH + chBase + tx] = tile[tx][ty + 8 * k];
    }
}

// ---------------- kernel 2: project grid vertices through each camera -------
__global__ void oft_project(const float* __restrict__ ks,
                            const float* __restrict__ imu2cs,
                            const float* __restrict__ prs,
                            const float* __restrict__ ptr_,
                            const float* __restrict__ und,
                            const float* __restrict__ grid) {
    const int idx = blockIdx.x * blockDim.x + threadIdx.x;
    if (idx >= NCAM * NY * ZD * XD) return;
    const int xi  = idx % XD;
    const int zi  = (idx / XD) % ZD;
    const int ny  = (idx / (XD * ZD)) % NY;
    const int cam = idx / (XD * ZD * NY);

    const float* K = ks + cam * 9;
    const float* M = imu2cs + cam * 12;
    float cal[12];
    #pragma unroll
    for (int i = 0; i < 3; ++i)
        #pragma unroll
        for (int j = 0; j < 4; ++j)
            cal[i * 4 + j] = K[i * 3 + 0] * M[0 * 4 + j]
                           + K[i * 3 + 1] * M[1 * 4 + j]
                           + K[i * 3 + 2] * M[2 * 4 + j];

    const float* g = grid + (size_t)(zi * XD + xi) * 3;
    const float X = g[0];
    const float Y = g[1] + (2.0f - (float)ny);   // ys = -arange(0,4)+2
    const float Z = g[2];

    float hx = cal[0] * X + cal[1] * Y + cal[2]  * Z + cal[3];
    float hy = cal[4] * X + cal[5] * Y + cal[6]  * Z + cal[7];
    float hz = cal[8] * X + cal[9] * Y + cal[10] * Z + cal[11];
    const bool pos = hz > 0.f;
    if (!pos) { hx = 0.f; hy = 0.f; }
    const float px = hx / hz;
    const float py = hy / hz;

    const float fx = K[0], fy = K[4], cx = K[2], cy = K[5];
    const float* D = und + cam * 7;
    const float x = (px - cx) / fx;
    const float y = (py - cy) / fy;
    float xd, yd;
    if (D[6] == 1.0f) {                          // fisheye
        const float r  = sqrtf(x * x + y * y);
        const float th = atanf(r);
        const float t2 = th * th, t4 = t2 * t2, t6 = t4 * t2, t8 = t4 * t4;
        const float rad = th * (1.f + D[0] * t2 + D[1] * t4 + D[2] * t6 + D[5] * t8) / r;
        xd = x * rad * fx + cx;
        yd = y * rad * fy + cy;
    } else {                                     // pinhole + tangential
        const float k1 = D[0], k2 = D[1], k3 = D[2], p1 = D[3], p2 = D[4];
        const float r2 = x * x + y * y;
        const float poly = 1.f + k1 * r2 + k2 * r2 * r2 + k3 * r2 * r2 * r2;
        const float xdd = x * poly + (2.f * p1 * x * y + p2 * (r2 + 2.f * x * x));
        const float ydd = y * poly + (p1 * (r2 + 2.f * y * y) + 2.f * p2 * x * y);
        xd = xdd * fx + cx;
        yd = ydd * fy + cy;
    }
    const float fl = pos ? 1.f : 0.f;
    xd *= fl; yd *= fl;

    const float* PR = prs + cam * 9;
    const float* PT = ptr_ + cam * 3;
    const float qx = PR[0] * xd + PR[1] * yd + PT[0];
    const float qy = PR[3] * xd + PR[4] * yd + PT[1];
    const float ncx = fminf(fmaxf(2.f * qx - 1.f, -1.f), 1.f);
    const float ncy = fminf(fmaxf(2.f * qy - 1.f, -1.f), 1.f);
    d_proj[idx] = make_float2(ncx, ncy);
}

// ---------------- kernel 3: box geometry -> separable 16-tap records --------
__device__ __forceinline__ void map_axis(float c, int extent,
                                         int& i0, int& i1, float& w) {
    const float lim = (float)(extent - 1);
    const float v = fminf(fmaxf((c + 1.f) * 0.5f * lim, 0.f), lim);
    const float f = floorf(v);
    i0 = (int)f;
    w = v - f;
    i1 = min(i0 + 1, extent - 1);
}

__global__ void oft_geometry() {
    const int idx = blockIdx.x * blockDim.x + threadIdx.x;
    if (idx >= NREC) return;
    const int p   = idx % P;
    const int nh  = (idx / P) % NH;
    const int cam = idx / (P * NH);
    const int wd = p % WDIM;
    const int d  = p / WDIM;

    float left = FLT_MAX, right = -FLT_MAX, top = FLT_MAX, bot = -FLT_MAX;
    #pragma unroll
    for (int a = 0; a < 2; ++a)
        #pragma unroll
        for (int b = 0; b < 2; ++b)
            #pragma unroll
            for (int c = 0; c < 2; ++c) {
                const float2 v = d_proj[((cam * NY + nh + a) * ZD + d + b) * XD + wd + c];
                left  = fminf(left,  v.x);  right = fmaxf(right, v.x);
                top   = fminf(top,   v.y);  bot   = fmaxf(bot,   v.y);
            }

    const float area = (right - left) * (bot - top) * ((float)HF * (float)WF * 0.25f) + EPS_F;
    const float sc = (area > EPS_F) ? (1.f / area) : 0.f;

    int xl0, xl1, xr0, xr1, yt0, yt1, yb0, yb1;
    float wxl, wxr, wyt, wyb;
    map_axis(left,  WF, xl0, xl1, wxl);
    map_axis(right, WF, xr0, xr1, wxr);
    map_axis(top,   HF, yt0, yt1, wyt);
    map_axis(bot,   HF, yb0, yb1, wyb);

    // value = sum_j wb_j * sum_i wa_i * I[yo_j + xi_i]  (tl+br-tr-bl separable)
    g_xi[idx] = make_int4(xl0, xl1, xr0, xr1);
    g_wa[idx] = make_float4(1.f - wxl, wxl, -(1.f - wxr), -wxr);
    g_yo[idx] = make_int4(yt0 * WF, yt1 * WF, yb0 * WF, yb1 * WF);
    g_wb[idx] = make_float4(1.f - wyt, wyt, -(1.f - wyb), -wyb);
    g_sc[idx] = sc;
}

// ---------------- kernel 4: gather + max over cameras (dominant) ------------
// One warp per (nh, p) point; lanes carry 2 channels each (64 ch / warp).
// Channel-last integral layout makes every tap a single coalesced 256B
// warp-load (LDG.64 x 32 lanes) = minimum-possible L1 wavefronts per byte.
// Records are warp-uniform broadcast loads. Degenerate boxes (sc==0)
// contribute exactly 0 to the camera-max, so their 16 taps are skipped.
__global__ void __launch_bounds__(256) oft_sample(float* __restrict__ out) {
    __shared__ float s_out[CCH][9];            // [ch][point-in-block], padded
    const int warp = threadIdx.x >> 5;
    const int lane = threadIdx.x & 31;
    const int pt = blockIdx.x * 8 + warp;      // 0 .. NH*P-1
    const int p  = pt & (P - 1);
    const int nh = pt >> 14;                   // P == 2^14

    float2 m = make_float2(-INFINITY, -INFINITY);

    for (int cam = 0; cam < NCAM; ++cam) {
        const int rec = (cam * NH + nh) * P + p;
        const float sc = g_sc[rec];
        if (sc != 0.f) {                       // warp-uniform branch
            const int4   xi = g_xi[rec];
            const int4   yo = g_yo[rec];
            const float4 wa = g_wa[rec];
            const float4 wb = g_wb[rec];
            // float2 view: 32 float2 per pixel, lane selects the channel pair
            const float2* base = reinterpret_cast<const float2*>(
                d_integT + (size_t)cam * SLICE * CCH) + lane;
            const int o0 = xi.x * 32, o1 = xi.y * 32, o2 = xi.z * 32, o3 = xi.w * 32;
            const int r0 = yo.x * 32, r1 = yo.y * 32, r2 = yo.z * 32, r3 = yo.w * 32;

            float2 acc = make_float2(0.f, 0.f);
            {
                const float2 t0 = __ldg(base + r0 + o0), t1 = __ldg(base + r0 + o1);
                const float2 t2 = __ldg(base + r0 + o2), t3 = __ldg(base + r0 + o3);
                acc.x += wb.x * (wa.x*t0.x + wa.y*t1.x + wa.z*t2.x + wa.w*t3.x);
                acc.y += wb.x * (wa.x*t0.y + wa.y*t1.y + wa.z*t2.y + wa.w*t3.y);
            }
            {
                const float2 t0 = __ldg(base + r1 + o0), t1 = __ldg(base + r1 + o1);
                const float2 t2 = __ldg(base + r1 + o2), t3 = __ldg(base + r1 + o3);
                acc.x += wb.y * (wa.x*t0.x + wa.y*t1.x + wa.z*t2.x + wa.w*t3.x);
                acc.y += wb.y * (wa.x*t0.y + wa.y*t1.y + wa.z*t2.y + wa.w*t3.y);
            }
            {
                const float2 t0 = __ldg(base + r2 + o0), t1 = __ldg(base + r2 + o1);
                const float2 t2 = __ldg(base + r2 + o2), t3 = __ldg(base + r2 + o3);
                acc.x += wb.z * (wa.x*t0.x + wa.y*t1.x + wa.z*t2.x + wa.w*t3.x);
                acc.y += wb.z * (wa.x*t0.y + wa.y*t1.y + wa.z*t2.y + wa.w*t3.y);
            }
            {
                const float2 t0 = __ldg(base + r3 + o0), t1 = __ldg(base + r3 + o1);
                const float2 t2 = __ldg(base + r3 + o2), t3 = __ldg(base + r3 + o3);
                acc.x += wb.w * (wa.x*t0.x + wa.y*t1.x + wa.z*t2.x + wa.w*t3.x);
                acc.y += wb.w * (wa.x*t0.y + wa.y*t1.y + wa.z*t2.y + wa.w*t3.y);
            }
            m.x = fmaxf(m.x, acc.x * sc);
            m.y = fmaxf(m.y, acc.y * sc);
        } else {
            m.x = fmaxf(m.x, 0.f);
            m.y = fmaxf(m.y, 0.f);
        }
    }

    s_out[lane * 2 + 0][warp] = m.x;
    s_out[lane * 2 + 1][warp] = m.y;
    __syncthreads();

    // coalesced store: out[ch][nh][p], 8 consecutive p per block
    const int p0  = (blockIdx.x * 8) & (P - 1);
    const int nhb = (blockIdx.x * 8) >> 14;
    #pragma unroll
    for (int r = 0; r < 2; ++r) {
        const int idx = threadIdx.x + r * 256;
        const int ch = idx >> 3, pp = idx & 7;
        out[((size_t)ch * NH + nhb) * P + p0 + pp] = s_out[ch][pp];
    }
}

// ---------------- launch --------------------------------------------------
extern "C" void kernel_launch(void* const* d_in, const int* in_sizes, int n_in,
                              void* d_out, int out_size) {
    const float* features  = (const float*)d_in[0];
    const float* ks        = (const float*)d_in[1];
    const float* imu2cs    = (const float*)d_in[2];
    const float* post_rots = (const float*)d_in[3];
    const float* post_tran = (const float*)d_in[4];
    const float* undists   = (const float*)d_in[5];
    const float* grid      = (const float*)d_in[6];
    float* out = (float*)d_out;

    oft_integral<<<NCAM * CCH, 256>>>(features);

    dim3 tgrid(SLICE / 32, CCH / 32, NCAM);    // 352 x 2 x 6
    oft_transpose<<<tgrid, dim3(32, 8)>>>();

    const int nproj = NCAM * NY * ZD * XD;
    oft_project<<<(nproj + 255) / 256, 256>>>(ks, imu2cs, post_rots, post_tran,
                                              undists, grid);

    oft_geometry<<<(NREC + 255) / 256, 256>>>();

    const int npts = NH * P;                   // 49152 warps
    oft_sample<<<npts / 8, 256>>>(out);
}

// round 6
// speedup vs baseline: 1.2347x; 1.2347x over previous
#include <cuda_runtime.h>
#include <math.h>
#include <float.h>

// ---------------- problem constants (fixed by setup_inputs) ----------------
static constexpr int NCAM = 6;
static constexpr int CCH  = 64;
static constexpr int HF   = 64;
static constexpr int WF   = 176;
static constexpr int SLICE = HF * WF;          // 11264
static constexpr int ZD   = 129;
static constexpr int XD   = 129;
static constexpr int NY   = 4;
static constexpr int NH   = 3;                 // NY-1
static constexpr int DD   = 128;               // ZD-1
static constexpr int WDIM = 128;               // XD-1
static constexpr int P    = DD * WDIM;         // 16384 = 2^14
static constexpr int NREC = NCAM * NH * P;     // 294912
static constexpr float EPS_F = 1e-6f;

// ---------------- device scratch (no dynamic allocation allowed) -----------
__device__ float  d_integ[NCAM * CCH * SLICE];       // integral, [cam][ch][pix]
__device__ float2 d_proj[NCAM * NY * ZD * XD];       // projected grid
__device__ int4   g_xi[NREC];                        // 4 column indices
__device__ int4   g_yo[NREC];                        // 4 row offsets (y*WF)
__device__ float4 g_wa[NREC];                        // 4 signed column weights
__device__ float4 g_wb[NREC];                        // 4 signed row weights
__device__ float  g_sc[NREC];                        // 1/area (0 if degenerate)

// ---------------- kernel 1: per-(cam,channel) 2D integral image -------------
__global__ void oft_integral(const float* __restrict__ feat) {
    __shared__ float sh[HF][WF + 1];   // +1 pad: conflict-free column phase
    const int s = blockIdx.x;          // 0..NCAM*CCH-1
    const float* src = feat + (size_t)s * SLICE;
    float* dst = d_integ + (size_t)s * SLICE;

    for (int i = threadIdx.x; i < SLICE; i += blockDim.x)
        sh[i / WF][i % WF] = src[i];
    __syncthreads();

    if (threadIdx.x < HF) {            // row-wise prefix sum
        float acc = 0.f;
        #pragma unroll 4
        for (int w = 0; w < WF; ++w) { acc += sh[threadIdx.x][w]; sh[threadIdx.x][w] = acc; }
    }
    __syncthreads();

    if (threadIdx.x < WF) {            // column-wise prefix sum
        float acc = 0.f;
        #pragma unroll 4
        for (int h = 0; h < HF; ++h) { acc += sh[h][threadIdx.x]; sh[h][threadIdx.x] = acc; }
    }
    __syncthreads();

    for (int i = threadIdx.x; i < SLICE; i += blockDim.x)
        dst[i] = sh[i / WF][i % WF];
}

// ---------------- kernel 2: project grid vertices through each camera -------
__global__ void oft_project(const float* __restrict__ ks,
                            const float* __restrict__ imu2cs,
                            const float* __restrict__ prs,
                            const float* __restrict__ ptr_,
                            const float* __restrict__ und,
                            const float* __restrict__ grid) {
    const int idx = blockIdx.x * blockDim.x + threadIdx.x;
    if (idx >= NCAM * NY * ZD * XD) return;
    const int xi  = idx % XD;
    const int zi  = (idx / XD) % ZD;
    const int ny  = (idx / (XD * ZD)) % NY;
    const int cam = idx / (XD * ZD * NY);

    const float* K = ks + cam * 9;
    const float* M = imu2cs + cam * 12;
    float cal[12];
    #pragma unroll
    for (int i = 0; i < 3; ++i)
        #pragma unroll
        for (int j = 0; j < 4; ++j)
            cal[i * 4 + j] = K[i * 3 + 0] * M[0 * 4 + j]
                           + K[i * 3 + 1] * M[1 * 4 + j]
                           + K[i * 3 + 2] * M[2 * 4 + j];

    const float* g = grid + (size_t)(zi * XD + xi) * 3;
    const float X = g[0];
    const float Y = g[1] + (2.0f - (float)ny);   // ys = -arange(0,4)+2
    const float Z = g[2];

    float hx = cal[0] * X + cal[1] * Y + cal[2]  * Z + cal[3];
    float hy = cal[4] * X + cal[5] * Y + cal[6]  * Z + cal[7];
    float hz = cal[8] * X + cal[9] * Y + cal[10] * Z + cal[11];
    const bool pos = hz > 0.f;
    if (!pos) { hx = 0.f; hy = 0.f; }            // flag zeroes x,y behind cam
    const float px = hx / hz;
    const float py = hy / hz;

    const float fx = K[0], fy = K[4], cx = K[2], cy = K[5];
    const float* D = und + cam * 7;
    const float x = (px - cx) / fx;
    const float y = (py - cy) / fy;
    float xd, yd;
    if (D[6] == 1.0f) {                          // fisheye
        const float r  = sqrtf(x * x + y * y);
        const float th = atanf(r);
        const float t2 = th * th, t4 = t2 * t2, t6 = t4 * t2, t8 = t4 * t4;
        const float rad = th * (1.f + D[0] * t2 + D[1] * t4 + D[2] * t6 + D[5] * t8) / r;
        xd = x * rad * fx + cx;
        yd = y * rad * fy + cy;
    } else {                                     // pinhole + tangential
        const float k1 = D[0], k2 = D[1], k3 = D[2], p1 = D[3], p2 = D[4];
        const float r2 = x * x + y * y;
        const float poly = 1.f + k1 * r2 + k2 * r2 * r2 + k3 * r2 * r2 * r2;
        const float xdd = x * poly + (2.f * p1 * x * y + p2 * (r2 + 2.f * x * x));
        const float ydd = y * poly + (p1 * (r2 + 2.f * y * y) + 2.f * p2 * x * y);
        xd = xdd * fx + cx;
        yd = ydd * fy + cy;
    }
    const float fl = pos ? 1.f : 0.f;
    xd *= fl; yd *= fl;

    const float* PR = prs + cam * 9;
    const float* PT = ptr_ + cam * 3;
    const float qx = PR[0] * xd + PR[1] * yd + PT[0];
    const float qy = PR[3] * xd + PR[4] * yd + PT[1];
    const float ncx = fminf(fmaxf(2.f * qx - 1.f, -1.f), 1.f);
    const float ncy = fminf(fmaxf(2.f * qy - 1.f, -1.f), 1.f);
    d_proj[idx] = make_float2(ncx, ncy);
}

// ---------------- kernel 3: box geometry -> separable 16-tap records --------
// One block per (cam, nh, d) row: stage the 2x2x129 projected vertices in
// smem (coalesced loads, 4x less traffic than per-thread gathering), then
// 128 threads emit one record each.
__device__ __forceinline__ void map_axis(float c, int extent,
                                         int& i0, int& i1, float& w) {
    const float lim = (float)(extent - 1);
    const float v = fminf(fmaxf((c + 1.f) * 0.5f * lim, 0.f), lim);
    const float f = floorf(v);
    i0 = (int)f;
    w = v - f;
    i1 = min(i0 + 1, extent - 1);
}

__global__ void __launch_bounds__(128) oft_geometry() {
    __shared__ float2 sp[2][2][XD];    // [ny][z][x]
    const int blk = blockIdx.x;        // (cam*NH + nh)*DD + d
    const int d   = blk % DD;
    const int nh  = (blk / DD) % NH;
    const int cam = blk / (DD * NH);

    for (int i = threadIdx.x; i < 2 * 2 * XD; i += blockDim.x) {
        const int x = i % XD;
        const int b = (i / XD) & 1;
        const int a = i / (XD * 2);
        sp[a][b][x] = d_proj[((cam * NY + nh + a) * ZD + d + b) * XD + x];
    }
    __syncthreads();

    const int wd = threadIdx.x;
    float left = FLT_MAX, right = -FLT_MAX, top = FLT_MAX, bot = -FLT_MAX;
    #pragma unroll
    for (int a = 0; a < 2; ++a)
        #pragma unroll
        for (int b = 0; b < 2; ++b)
            #pragma unroll
            for (int c = 0; c < 2; ++c) {
                const float2 v = sp[a][b][wd + c];
                left  = fminf(left,  v.x);  right = fmaxf(right, v.x);
                top   = fminf(top,   v.y);  bot   = fmaxf(bot,   v.y);
            }

    const float area = (right - left) * (bot - top) * ((float)HF * (float)WF * 0.25f) + EPS_F;
    const float sc = (area > EPS_F) ? (1.f / area) : 0.f;

    int xl0, xl1, xr0, xr1, yt0, yt1, yb0, yb1;
    float wxl, wxr, wyt, wyb;
    map_axis(left,  WF, xl0, xl1, wxl);
    map_axis(right, WF, xr0, xr1, wxr);
    map_axis(top,   HF, yt0, yt1, wyt);
    map_axis(bot,   HF, yb0, yb1, wyb);

    const int idx = (cam * NH + nh) * P + d * WDIM + wd;
    // value = sum_j wb_j * sum_i wa_i * I[yo_j + xi_i]  (tl+br-tr-bl separable)
    g_xi[idx] = make_int4(xl0, xl1, xr0, xr1);
    g_wa[idx] = make_float4(1.f - wxl, wxl, -(1.f - wxr), -wxr);
    g_yo[idx] = make_int4(yt0 * WF, yt1 * WF, yb0 * WF, yb1 * WF);
    g_wb[idx] = make_float4(1.f - wyt, wyt, -(1.f - wyb), -wyb);
    g_sc[idx] = sc;
}

// ---------------- kernel 4: gather + max over cameras (dominant) ------------
// R3 layout (proven L1-friendly): 4 channels per thread, consecutive threads
// = consecutive wd so a warp's taps share cache lines heavily (L1 serves ~80%
// of traffic). NEW: degenerate boxes (sc==0 => reference value exactly 0)
// skip all 16 taps — out-of-FOV (cam,point) pairs are a large fraction with
// these yawed cameras, and the kernel is L1-wavefront-bound so time scales
// with surviving taps. The branch is spatially coherent => near warp-uniform.
__global__ void __launch_bounds__(256) oft_sample(float* __restrict__ out) {
    const int t = blockIdx.x * blockDim.x + threadIdx.x;
    const int p  = t & (P - 1);
    const int nh = (t >> 14) % NH;
    const int cq = t / (P * NH);          // channel quad 0..15

    float m[4] = {-INFINITY, -INFINITY, -INFINITY, -INFINITY};

    #pragma unroll
    for (int cam = 0; cam < NCAM; ++cam) {
        const int rec = (cam * NH + nh) * P + p;
        const float sc = __ldg(&g_sc[rec]);
        if (sc != 0.f) {
            const int4   xi = __ldg(&g_xi[rec]);
            const int4   yo = __ldg(&g_yo[rec]);
            const float4 wa = __ldg(&g_wa[rec]);
            const float4 wb = __ldg(&g_wb[rec]);
            const float* base = d_integ + (size_t)(cam * CCH + cq * 4) * SLICE;

            #pragma unroll
            for (int u = 0; u < 4; ++u) {
                const float* bu = base + (size_t)u * SLICE;
                const float s0 = wa.x * __ldg(bu + yo.x + xi.x) + wa.y * __ldg(bu + yo.x + xi.y)
                               + wa.z * __ldg(bu + yo.x + xi.z) + wa.w * __ldg(bu + yo.x + xi.w);
                const float s1 = wa.x * __ldg(bu + yo.y + xi.x) + wa.y * __ldg(bu + yo.y + xi.y)
                               + wa.z * __ldg(bu + yo.y + xi.z) + wa.w * __ldg(bu + yo.y + xi.w);
                const float s2 = wa.x * __ldg(bu + yo.z + xi.x) + wa.y * __ldg(bu + yo.z + xi.y)
                               + wa.z * __ldg(bu + yo.z + xi.z) + wa.w * __ldg(bu + yo.z + xi.w);
                const float s3 = wa.x * __ldg(bu + yo.w + xi.x) + wa.y * __ldg(bu + yo.w + xi.y)
                               + wa.z * __ldg(bu + yo.w + xi.z) + wa.w * __ldg(bu + yo.w + xi.w);
                const float acc = wb.x * s0 + wb.y * s1 + wb.z * s2 + wb.w * s3;
                m[u] = fmaxf(m[u], acc * sc);
            }
        } else {
            #pragma unroll
            for (int u = 0; u < 4; ++u) m[u] = fmaxf(m[u], 0.f);
        }
    }

    #pragma unroll
    for (int u = 0; u < 4; ++u)
        out[(size_t)((cq * 4 + u) * NH + nh) * P + p] = m[u];
}

// ---------------- launch --------------------------------------------------
extern "C" void kernel_launch(void* const* d_in, const int* in_sizes, int n_in,
                              void* d_out, int out_size) {
    const float* features  = (const float*)d_in[0];
    const float* ks        = (const float*)d_in[1];
    const float* imu2cs    = (const float*)d_in[2];
    const float* post_rots = (const float*)d_in[3];
    const float* post_tran = (const float*)d_in[4];
    const float* undists   = (const float*)d_in[5];
    const float* grid      = (const float*)d_in[6];
    float* out = (float*)d_out;

    oft_integral<<<NCAM * CCH, 256>>>(features);

    const int nproj = NCAM * NY * ZD * XD;
    oft_project<<<(nproj + 255) / 256, 256>>>(ks, imu2cs, post_rots, post_tran,
                                              undists, grid);

    oft_geometry<<<NCAM * NH * DD, 128>>>();

    const int nsamp = (CCH / 4) * NH * P;      // 786432 threads
    oft_sample<<<(nsamp + 255) / 256, 256>>>(out);
}

// round 7
// speedup vs baseline: 1.5076x; 1.2211x over previous
#include <cuda_runtime.h>
#include <math.h>
#include <float.h>

// ---------------- problem constants (fixed by setup_inputs) ----------------
static constexpr int NCAM = 6;
static constexpr int CCH  = 64;
static constexpr int NCQ  = CCH / 4;           // 16 channel quads
static constexpr int HF   = 64;
static constexpr int WF   = 176;
static constexpr int SLICE = HF * WF;          // 11264
static constexpr int ZD   = 129;
static constexpr int XD   = 129;
static constexpr int NY   = 4;
static constexpr int NH   = 3;                 // NY-1
static constexpr int DD   = 128;               // ZD-1
static constexpr int WDIM = 128;               // XD-1
static constexpr int P    = DD * WDIM;         // 16384 = 2^14
static constexpr int NREC = NCAM * NH * P;     // 294912
static constexpr float EPS_F = 1e-6f;

// ---------------- device scratch (no dynamic allocation allowed) -----------
// Integral images, channel-quad interleaved: [cam][cq][pix][4ch]. One LDG.128
// per tap serves 4 channels (4x fewer load instrs, ~2-3x fewer L1 wavefronts).
__device__ float  d_integ4[NCAM * NCQ * SLICE * 4];  // ~17.3 MB
__device__ float2 d_proj[NCAM * NY * ZD * XD];       // projected grid
__device__ int4   g_xi[NREC];                        // 4 column indices
__device__ int4   g_yo[NREC];                        // 4 row offsets (y*WF)
__device__ float4 g_wa[NREC];                        // 4 signed column weights
__device__ float4 g_wb[NREC];                        // 4 signed row weights
__device__ float  g_sc[NREC];                        // 1/area (0 if degenerate)

// ---------------- kernel 1: integral image + interleaved store --------------
__global__ void oft_integral(const float* __restrict__ feat) {
    __shared__ float sh[HF][WF + 1];   // +1 pad: conflict-free column phase
    const int s = blockIdx.x;          // 0..NCAM*CCH-1
    const int cam = s / CCH;
    const int ch  = s % CCH;
    const float* src = feat + (size_t)s * SLICE;
    // strided 4B stores into the float4-interleaved layout (stays in L2)
    float* dst = d_integ4 + ((size_t)(cam * NCQ + (ch >> 2)) * SLICE) * 4 + (ch & 3);

    for (int i = threadIdx.x; i < SLICE; i += blockDim.x)
        sh[i / WF][i % WF] = src[i];
    __syncthreads();

    if (threadIdx.x < HF) {            // row-wise prefix sum
        float acc = 0.f;
        #pragma unroll 4
        for (int w = 0; w < WF; ++w) { acc += sh[threadIdx.x][w]; sh[threadIdx.x][w] = acc; }
    }
    __syncthreads();

    if (threadIdx.x < WF) {            // column-wise prefix sum
        float acc = 0.f;
        #pragma unroll 4
        for (int h = 0; h < HF; ++h) { acc += sh[h][threadIdx.x]; sh[h][threadIdx.x] = acc; }
    }
    __syncthreads();

    for (int i = threadIdx.x; i < SLICE; i += blockDim.x)
        dst[(size_t)i * 4] = sh[i / WF][i % WF];
}

// ---------------- kernel 2: project grid vertices through each camera -------
__global__ void oft_project(const float* __restrict__ ks,
                            const float* __restrict__ imu2cs,
                            const float* __restrict__ prs,
                            const float* __restrict__ ptr_,
                            const float* __restrict__ und,
                            const float* __restrict__ grid) {
    const int idx = blockIdx.x * blockDim.x + threadIdx.x;
    if (idx >= NCAM * NY * ZD * XD) return;
    const int xi  = idx % XD;
    const int zi  = (idx / XD) % ZD;
    const int ny  = (idx / (XD * ZD)) % NY;
    const int cam = idx / (XD * ZD * NY);

    const float* K = ks + cam * 9;
    const float* M = imu2cs + cam * 12;
    float cal[12];
    #pragma unroll
    for (int i = 0; i < 3; ++i)
        #pragma unroll
        for (int j = 0; j < 4; ++j)
            cal[i * 4 + j] = K[i * 3 + 0] * M[0 * 4 + j]
                           + K[i * 3 + 1] * M[1 * 4 + j]
                           + K[i * 3 + 2] * M[2 * 4 + j];

    const float* g = grid + (size_t)(zi * XD + xi) * 3;
    const float X = g[0];
    const float Y = g[1] + (2.0f - (float)ny);   // ys = -arange(0,4)+2
    const float Z = g[2];

    float hx = cal[0] * X + cal[1] * Y + cal[2]  * Z + cal[3];
    float hy = cal[4] * X + cal[5] * Y + cal[6]  * Z + cal[7];
    float hz = cal[8] * X + cal[9] * Y + cal[10] * Z + cal[11];
    const bool pos = hz > 0.f;
    if (!pos) { hx = 0.f; hy = 0.f; }            // flag zeroes x,y behind cam
    const float px = hx / hz;
    const float py = hy / hz;

    const float fx = K[0], fy = K[4], cx = K[2], cy = K[5];
    const float* D = und + cam * 7;
    const float x = (px - cx) / fx;
    const float y = (py - cy) / fy;
    float xd, yd;
    if (D[6] == 1.0f) {                          // fisheye
        const float r  = sqrtf(x * x + y * y);
        const float th = atanf(r);
        const float t2 = th * th, t4 = t2 * t2, t6 = t4 * t2, t8 = t4 * t4;
        const float rad = th * (1.f + D[0] * t2 + D[1] * t4 + D[2] * t6 + D[5] * t8) / r;
        xd = x * rad * fx + cx;
        yd = y * rad * fy + cy;
    } else {                                     // pinhole + tangential
        const float k1 = D[0], k2 = D[1], k3 = D[2], p1 = D[3], p2 = D[4];
        const float r2 = x * x + y * y;
        const float poly = 1.f + k1 * r2 + k2 * r2 * r2 + k3 * r2 * r2 * r2;
        const float xdd = x * poly + (2.f * p1 * x * y + p2 * (r2 + 2.f * x * x));
        const float ydd = y * poly + (p1 * (r2 + 2.f * y * y) + 2.f * p2 * x * y);
        xd = xdd * fx + cx;
        yd = ydd * fy + cy;
    }
    const float fl = pos ? 1.f : 0.f;
    xd *= fl; yd *= fl;

    const float* PR = prs + cam * 9;
    const float* PT = ptr_ + cam * 3;
    const float qx = PR[0] * xd + PR[1] * yd + PT[0];
    const float qy = PR[3] * xd + PR[4] * yd + PT[1];
    const float ncx = fminf(fmaxf(2.f * qx - 1.f, -1.f), 1.f);
    const float ncy = fminf(fmaxf(2.f * qy - 1.f, -1.f), 1.f);
    d_proj[idx] = make_float2(ncx, ncy);
}

// ---------------- kernel 3: box geometry -> separable 16-tap records --------
__device__ __forceinline__ void map_axis(float c, int extent,
                                         int& i0, int& i1, float& w) {
    const float lim = (float)(extent - 1);
    const float v = fminf(fmaxf((c + 1.f) * 0.5f * lim, 0.f), lim);
    const float f = floorf(v);
    i0 = (int)f;
    w = v - f;
    i1 = min(i0 + 1, extent - 1);
}

__global__ void __launch_bounds__(128) oft_geometry() {
    __shared__ float2 sp[2][2][XD];    // [ny][z][x]
    const int blk = blockIdx.x;        // (cam*NH + nh)*DD + d
    const int d   = blk % DD;
    const int nh  = (blk / DD) % NH;
    const int cam = blk / (DD * NH);

    for (int i = threadIdx.x; i < 2 * 2 * XD; i += blockDim.x) {
        const int x = i % XD;
        const int b = (i / XD) & 1;
        const int a = i / (XD * 2);
        sp[a][b][x] = d_proj[((cam * NY + nh + a) * ZD + d + b) * XD + x];
    }
    __syncthreads();

    const int wd = threadIdx.x;
    float left = FLT_MAX, right = -FLT_MAX, top = FLT_MAX, bot = -FLT_MAX;
    #pragma unroll
    for (int a = 0; a < 2; ++a)
        #pragma unroll
        for (int b = 0; b < 2; ++b)
            #pragma unroll
            for (int c = 0; c < 2; ++c) {
                const float2 v = sp[a][b][wd + c];
                left  = fminf(left,  v.x);  right = fmaxf(right, v.x);
                top   = fminf(top,   v.y);  bot   = fmaxf(bot,   v.y);
            }

    const float area = (right - left) * (bot - top) * ((float)HF * (float)WF * 0.25f) + EPS_F;
    const float sc = (area > EPS_F) ? (1.f / area) : 0.f;

    int xl0, xl1, xr0, xr1, yt0, yt1, yb0, yb1;
    float wxl, wxr, wyt, wyb;
    map_axis(left,  WF, xl0, xl1, wxl);
    map_axis(right, WF, xr0, xr1, wxr);
    map_axis(top,   HF, yt0, yt1, wyt);
    map_axis(bot,   HF, yb0, yb1, wyb);

    const int idx = (cam * NH + nh) * P + d * WDIM + wd;
    // value = sum_j wb_j * sum_i wa_i * I[yo_j + xi_i]  (tl+br-tr-bl separable)
    g_xi[idx] = make_int4(xl0, xl1, xr0, xr1);
    g_wa[idx] = make_float4(1.f - wxl, wxl, -(1.f - wxr), -wxr);
    g_yo[idx] = make_int4(yt0 * WF, yt1 * WF, yb0 * WF, yb1 * WF);
    g_wb[idx] = make_float4(1.f - wyt, wyt, -(1.f - wyb), -wyb);
    g_sc[idx] = sc;
}

// ---------------- float4 helpers -------------------------------------------
__device__ __forceinline__ float4 f4_scale(float s, float4 a) {
    return make_float4(s * a.x, s * a.y, s * a.z, s * a.w);
}
__device__ __forceinline__ float4 f4_fma(float s, float4 a, float4 acc) {
    return make_float4(fmaf(s, a.x, acc.x), fmaf(s, a.y, acc.y),
                       fmaf(s, a.z, acc.z), fmaf(s, a.w, acc.w));
}

// ---------------- kernel 4: gather + max over cameras (dominant) ------------
// R3 locality (lanes = adjacent wd -> heavy intra-warp line sharing) + one
// LDG.128 per tap serving 4 channels via the interleaved integral layout.
// 16 vector loads per (point,cam) instead of 64 scalar loads.
__global__ void __launch_bounds__(256) oft_sample(float* __restrict__ out) {
    const int t = blockIdx.x * blockDim.x + threadIdx.x;
    const int p  = t & (P - 1);
    const int nh = (t >> 14) % NH;
    const int cq = t / (P * NH);          // channel quad 0..15

    float4 m = make_float4(-INFINITY, -INFINITY, -INFINITY, -INFINITY);

    #pragma unroll
    for (int cam = 0; cam < NCAM; ++cam) {
        const int rec = (cam * NH + nh) * P + p;
        const float sc = __ldg(&g_sc[rec]);
        if (sc != 0.f) {
            const int4   xi = __ldg(&g_xi[rec]);
            const int4   yo = __ldg(&g_yo[rec]);
            const float4 wa = __ldg(&g_wa[rec]);
            const float4 wb = __ldg(&g_wb[rec]);
            const float4* base = reinterpret_cast<const float4*>(d_integ4)
                               + (size_t)(cam * NCQ + cq) * SLICE;

            float4 acc;
            {
                const float4* r = base + yo.x;
                float4 s = f4_scale(wa.x, __ldg(r + xi.x));
                s = f4_fma(wa.y, __ldg(r + xi.y), s);
                s = f4_fma(wa.z, __ldg(r + xi.z), s);
                s = f4_fma(wa.w, __ldg(r + xi.w), s);
                acc = f4_scale(wb.x, s);
            }
            {
                const float4* r = base + yo.y;
                float4 s = f4_scale(wa.x, __ldg(r + xi.x));
                s = f4_fma(wa.y, __ldg(r + xi.y), s);
                s = f4_fma(wa.z, __ldg(r + xi.z), s);
                s = f4_fma(wa.w, __ldg(r + xi.w), s);
                acc = f4_fma(wb.y, s, acc);
            }
            {
                const float4* r = base + yo.z;
                float4 s = f4_scale(wa.x, __ldg(r + xi.x));
                s = f4_fma(wa.y, __ldg(r + xi.y), s);
                s = f4_fma(wa.z, __ldg(r + xi.z), s);
                s = f4_fma(wa.w, __ldg(r + xi.w), s);
                acc = f4_fma(wb.z, s, acc);
            }
            {
                const float4* r = base + yo.w;
                float4 s = f4_scale(wa.x, __ldg(r + xi.x));
                s = f4_fma(wa.y, __ldg(r + xi.y), s);
                s = f4_fma(wa.z, __ldg(r + xi.z), s);
                s = f4_fma(wa.w, __ldg(r + xi.w), s);
                acc = f4_fma(wb.w, s, acc);
            }
            m.x = fmaxf(m.x, acc.x * sc);
            m.y = fmaxf(m.y, acc.y * sc);
            m.z = fmaxf(m.z, acc.z * sc);
            m.w = fmaxf(m.w, acc.w * sc);
        } else {
            m.x = fmaxf(m.x, 0.f);
            m.y = fmaxf(m.y, 0.f);
            m.z = fmaxf(m.z, 0.f);
            m.w = fmaxf(m.w, 0.f);
        }
    }

    float* o = out + (size_t)(cq * 4 * NH + nh) * P + p;
    o[0]                  = m.x;
    o[(size_t)NH * P]     = m.y;
    o[(size_t)2 * NH * P] = m.z;
    o[(size_t)3 * NH * P] = m.w;
}

// ---------------- launch --------------------------------------------------
extern "C" void kernel_launch(void* const* d_in, const int* in_sizes, int n_in,
                              void* d_out, int out_size) {
    const float* features  = (const float*)d_in[0];
    const float* ks        = (const float*)d_in[1];
    const float* imu2cs    = (const float*)d_in[2];
    const float* post_rots = (const float*)d_in[3];
    const float* post_tran = (const float*)d_in[4];
    const float* undists   = (const float*)d_in[5];
    const float* grid      = (const float*)d_in[6];
    float* out = (float*)d_out;

    oft_integral<<<NCAM * CCH, 256>>>(features);

    const int nproj = NCAM * NY * ZD * XD;
    oft_project<<<(nproj + 255) / 256, 256>>>(ks, imu2cs, post_rots, post_tran,
                                              undists, grid);

    oft_geometry<<<NCAM * NH * DD, 128>>>();

    const int nsamp = NCQ * NH * P;            // 786432 threads
    oft_sample<<<(nsamp + 255) / 256, 256>>>(out);
}